// round 3
// baseline (speedup 1.0000x reference)
#include <cuda_runtime.h>

#define W 512
#define BX 32
#define BY 8

// scratch (no allocations allowed)
__device__ float2  g_hsum[W * W];
__device__ float2  g_base[W * W];   // (Xbase, ybase)
__device__ float2  g_det [W * W];   // (Xdet,  ydet)
__device__ unsigned g_red[2];       // encoded min / max of y
__device__ float    g_C;            // -4*log2(e)/sigma^2

__device__ __forceinline__ unsigned enc(float f) {
    unsigned u = __float_as_uint(f);
    return (u & 0x80000000u) ? ~u : (u | 0x80000000u);
}
__device__ __forceinline__ float dec(unsigned e) {
    return (e & 0x80000000u) ? __uint_as_float(e ^ 0x80000000u)
                             : __uint_as_float(~e);
}
__device__ __forceinline__ float ex2(float a) {
    float r;
    asm("ex2.approx.f32 %0, %1;" : "=f"(r) : "f"(a));
    return r;
}

__global__ void k_init() { g_red[0] = 0xFFFFFFFFu; g_red[1] = 0u; }

__global__ void k_reduce(const float* __restrict__ y, int n) {
    float lmin = 3.4e38f, lmax = -3.4e38f;
    for (int idx = blockIdx.x * blockDim.x + threadIdx.x; idx < n;
         idx += gridDim.x * blockDim.x) {
        float v = y[idx];
        lmin = fminf(lmin, v);
        lmax = fmaxf(lmax, v);
    }
    #pragma unroll
    for (int o = 16; o; o >>= 1) {
        lmin = fminf(lmin, __shfl_xor_sync(0xFFFFFFFFu, lmin, o));
        lmax = fmaxf(lmax, __shfl_xor_sync(0xFFFFFFFFu, lmax, o));
    }
    __shared__ float smin[8], smax[8];
    int w = threadIdx.x >> 5, l = threadIdx.x & 31;
    if (l == 0) { smin[w] = lmin; smax[w] = lmax; }
    __syncthreads();
    if (threadIdx.x == 0) {
        float m = smin[0], M = smax[0];
        for (int k = 1; k < (int)(blockDim.x >> 5); k++) {
            m = fminf(m, smin[k]);
            M = fmaxf(M, smax[k]);
        }
        atomicMin(&g_red[0], enc(m));
        atomicMax(&g_red[1], enc(M));
    }
}

__global__ void k_final(const float* __restrict__ r) {
    float mn = dec(g_red[0]), mx = dec(g_red[1]);
    float sigma = r[0] * (mx - mn);
    g_C = -4.0f * 1.4426950408889634f / (sigma * sigma);
}

// horizontal 9-tap sum (zero pad)
__global__ void k_hbox(const float* __restrict__ X, const float* __restrict__ Y) {
    int j = blockIdx.x * blockDim.x + threadIdx.x;
    int i = blockIdx.y;
    if (j >= W) return;
    float sx = 0.f, sy = 0.f;
    #pragma unroll
    for (int dc = -4; dc <= 4; dc++) {
        int c = j + dc;
        if (c >= 0 && c < W) { sx += X[i * W + c]; sy += Y[i * W + c]; }
    }
    g_hsum[i * W + j] = make_float2(sx, sy);
}

// vertical 9-tap sum, /81, base + detail
__global__ void k_vbox(const float* __restrict__ X, const float* __restrict__ Y) {
    int j = blockIdx.x * blockDim.x + threadIdx.x;
    int i = blockIdx.y;
    if (j >= W) return;
    float sx = 0.f, sy = 0.f;
    #pragma unroll
    for (int dr = -4; dr <= 4; dr++) {
        int rr = i + dr;
        if (rr >= 0 && rr < W) {
            float2 h = g_hsum[rr * W + j];
            sx += h.x; sy += h.y;
        }
    }
    float bx = sx * (1.0f / 81.0f);
    float by = sy * (1.0f / 81.0f);
    int idx = i * W + j;
    g_base[idx] = make_float2(bx, by);
    g_det [idx] = make_float2(X[idx] - bx, Y[idx] - by);
}

__global__ __launch_bounds__(BX * BY)
void k_main(float* __restrict__ out) {
    __shared__ float2 tB[BY + 18][BX + 18];  // 26 x 50, base (halo 9)
    __shared__ float2 tD[BY + 4][BX + 8];    // 12 x 40, detail (halo 2/4)

    const int tx = threadIdx.x, ty = threadIdx.y;
    const int j0 = blockIdx.x * BX, i0 = blockIdx.y * BY;
    const int tid = ty * BX + tx;

    for (int t = tid; t < (BY + 18) * (BX + 18); t += BX * BY) {
        int rr = t / (BX + 18), cc = t % (BX + 18);
        int gi = i0 - 9 + rr, gj = j0 - 9 + cc;
        float2 v = make_float2(0.f, 0.f);
        if (gi >= 0 && gi < W && gj >= 0 && gj < W) v = g_base[gi * W + gj];
        tB[rr][cc] = v;
    }
    for (int t = tid; t < (BY + 4) * (BX + 8); t += BX * BY) {
        int rr = t / (BX + 8), cc = t % (BX + 8);
        int gi = i0 - 2 + rr, gj = j0 - 4 + cc;
        float2 v = make_float2(0.f, 0.f);
        if (gi >= 0 && gi < W && gj >= 0 && gj < W) v = g_det[gi * W + gj];
        tD[rr][cc] = v;
    }
    __syncthreads();

    const int i = i0 + ty, j = j0 + tx;
    // chunk mapping: chunks start at 62k, width 64 (last 16). Output col j
    // belongs to chunk 0 for j<=62, chunk 8 for j>=497, else (j-1)/62.
    int chunk = (j <= 62) ? 0 : ((j >= 497) ? 8 : (j - 1) / 62);
    int s = 62 * chunk;
    int e = (chunk == 8) ? W : s + 64;
    const float C = g_C;

    // ---- detail branch: 5x9 bilateral on (Xdet), value (ydet - Xdet) ----
    const float2 cd = tD[ty + 2][tx + 4];
    float wsD = 0.f, accD = 0.f;
    #pragma unroll 1
    for (int dr = -2; dr <= 2; dr++) {
        int r = i + dr;
        if (r < 0 || r >= W) continue;
        #pragma unroll
        for (int dc = -4; dc <= 4; dc++) {
            int c = j + dc;
            bool cv = (c >= s) && (c < e);
            float2 v = tD[ty + 2 + dr][tx + 4 + dc];
            float d = v.x - cd.x;
            float sp = -(float)(dr * dr + dc * dc) *
                       (1.4426950408889634f / 126.5625f);
            float w = ex2(fmaf(d * d, C, sp));
            w = cv ? w : 0.0f;
            wsD += w;
            accD = fmaf(w, v.y - v.x, accD);
        }
    }
    float bdet = accD / wsD;

    // ---- base branch: 19x19 bilateral-weighted guided filter ----
    const float2 cb = tB[ty + 9][tx + 9];
    float ws = 0.f, sx = 0.f, sy = 0.f, sxx = 0.f, sxy = 0.f;
    #pragma unroll 1
    for (int dr = -9; dr <= 9; dr++) {
        int r = i + dr;
        if (r < 0 || r >= W) continue;
        #pragma unroll
        for (int dc = -9; dc <= 9; dc++) {
            int c = j + dc;
            bool cv = (c >= s) && (c < e);
            float2 v = tB[ty + 9 + dr][tx + 9 + dc];
            float d = v.x - cb.x;
            float sp = -(float)(dr * dr + dc * dc) *
                       (1.4426950408889634f / 8145.0625f);
            float w = ex2(fmaf(d * d, C, sp));
            w = cv ? w : 0.0f;
            ws += w;
            float t = w * v.x;
            sx += t;
            sy  = fmaf(w, v.y, sy);
            sxx = fmaf(t, v.x, sxx);
            sxy = fmaf(t, v.y, sxy);
        }
    }
    float rw  = 1.0f / ws;
    float mx  = sx * rw, my = sy * rw;
    float varx = fmaf(sxx, rw, -mx * mx);
    float cov  = fmaf(sxy, rw, -mx * my);
    float A = cov / (varx + 1e-6f);
    float b = my - A * mx;
    out[i * W + j] = fmaf(A, cb.x, b) + cd.x + bdet;
}

extern "C" void kernel_launch(void* const* d_in, const int* in_sizes, int n_in,
                              void* d_out, int out_size) {
    const float* X = (const float*)d_in[0];
    const float* Y = (const float*)d_in[1];
    const float* r = (const float*)d_in[2];
    float* out = (float*)d_out;

    k_init<<<1, 1>>>();
    k_reduce<<<256, 256>>>(Y, W * W);
    k_final<<<1, 1>>>(r);

    dim3 b1(256), g1(W / 256, W);
    k_hbox<<<g1, b1>>>(X, Y);
    k_vbox<<<g1, b1>>>(X, Y);

    dim3 b2(BX, BY), g2(W / BX, W / BY);
    k_main<<<g2, b2>>>(out);
}

// round 5
// speedup vs baseline: 1.1686x; 1.1686x over previous
#include <cuda_runtime.h>

#define W 512
#define BX 32
#define BY 8

// -------- scratch (no allocations allowed) --------
__device__ float  g_baseX[W * W];
__device__ float  g_baseY[W * W];
__device__ float  g_detX [W * W];
__device__ float  g_detY [W * W];
__device__ float2 g_part[256];     // per-block (min,max) of y
__device__ int    g_count = 0;     // arrival counter (self-resetting)
__device__ float  g_C;             // -4*log2(e)/sigma^2

#define KB (1.4426950408889634f / 8145.0625f)   // base spatial, log2 units
#define KD (1.4426950408889634f / 126.5625f)    // detail spatial, log2 units

typedef unsigned long long u64;

__device__ __forceinline__ float ex2f(float a) {
    float r; asm("ex2.approx.f32 %0, %1;" : "=f"(r) : "f"(a)); return r;
}
__device__ __forceinline__ u64 pk2(float lo, float hi) {
    u64 r; asm("mov.b64 %0, {%1, %2};" : "=l"(r) : "f"(lo), "f"(hi)); return r;
}
__device__ __forceinline__ void upk2(float& lo, float& hi, u64 v) {
    asm("mov.b64 {%0, %1}, %2;" : "=f"(lo), "=f"(hi) : "l"(v));
}
__device__ __forceinline__ u64 add2(u64 a, u64 b) {
    u64 r; asm("add.rn.f32x2 %0, %1, %2;" : "=l"(r) : "l"(a), "l"(b)); return r;
}
__device__ __forceinline__ u64 mul2(u64 a, u64 b) {
    u64 r; asm("mul.rn.f32x2 %0, %1, %2;" : "=l"(r) : "l"(a), "l"(b)); return r;
}
__device__ __forceinline__ u64 fma2(u64 a, u64 b, u64 c) {
    u64 r; asm("fma.rn.f32x2 %0, %1, %2, %3;" : "=l"(r) : "l"(a), "l"(b), "l"(c)); return r;
}

// ======================= prep: 9x9 box + base/detail + sigma =======================
// One block per 32x32 tile (grid 16x16). Also block-reduces y min/max; the last
// block to finish combines partials into g_C (and resets the counter so the
// kernel is graph-replay deterministic).
__global__ __launch_bounds__(256) void k_prep(const float* __restrict__ X,
                                              const float* __restrict__ Y,
                                              const float* __restrict__ r) {
    __shared__ float2 sIn[40][40];   // (X,Y) with halo 4
    __shared__ float2 sH[40][32];    // horizontal 9-sum
    __shared__ float  smin[8], smax[8];
    __shared__ int    isLast;

    const int tid = threadIdx.y * 32 + threadIdx.x;
    const int j0 = blockIdx.x * 32, i0 = blockIdx.y * 32;

    for (int t = tid; t < 40 * 40; t += 256) {
        int rr = t / 40, cc = t % 40;
        int gi = i0 - 4 + rr, gj = j0 - 4 + cc;
        float2 v = make_float2(0.f, 0.f);
        if ((unsigned)gi < W && (unsigned)gj < W) {
            v.x = X[gi * W + gj]; v.y = Y[gi * W + gj];
        }
        sIn[rr][cc] = v;
    }
    __syncthreads();

    for (int t = tid; t < 40 * 32; t += 256) {
        int rr = t / 32, cc = t % 32;
        float sx = 0.f, sy = 0.f;
        #pragma unroll
        for (int d = 0; d < 9; d++) { float2 v = sIn[rr][cc + d]; sx += v.x; sy += v.y; }
        sH[rr][cc] = make_float2(sx, sy);
    }
    __syncthreads();

    float lmin = 3.4e38f, lmax = -3.4e38f;
    for (int t = tid; t < 32 * 32; t += 256) {
        int rr = t / 32, cc = t % 32;
        float sx = 0.f, sy = 0.f;
        #pragma unroll
        for (int d = 0; d < 9; d++) { float2 v = sH[rr + d][cc]; sx += v.x; sy += v.y; }
        float bx = sx * (1.0f / 81.0f);
        float by = sy * (1.0f / 81.0f);
        float2 c = sIn[rr + 4][cc + 4];
        int idx = (i0 + rr) * W + (j0 + cc);
        g_baseX[idx] = bx;        g_baseY[idx] = by;
        g_detX [idx] = c.x - bx;  g_detY [idx] = c.y - by;
        lmin = fminf(lmin, c.y);  lmax = fmaxf(lmax, c.y);
    }

    #pragma unroll
    for (int o = 16; o; o >>= 1) {
        lmin = fminf(lmin, __shfl_xor_sync(0xFFFFFFFFu, lmin, o));
        lmax = fmaxf(lmax, __shfl_xor_sync(0xFFFFFFFFu, lmax, o));
    }
    int wid = tid >> 5, lid = tid & 31;
    if (lid == 0) { smin[wid] = lmin; smax[wid] = lmax; }
    __syncthreads();
    if (tid == 0) {
        float m = smin[0], M = smax[0];
        #pragma unroll
        for (int k = 1; k < 8; k++) { m = fminf(m, smin[k]); M = fmaxf(M, smax[k]); }
        g_part[blockIdx.y * 16 + blockIdx.x] = make_float2(m, M);
        __threadfence();
        int t = atomicAdd(&g_count, 1);
        isLast = (t == 255);
    }
    __syncthreads();
    if (isLast) {
        __threadfence();
        float2 p = g_part[tid];
        float m = p.x, M = p.y;
        #pragma unroll
        for (int o = 16; o; o >>= 1) {
            m = fminf(m, __shfl_xor_sync(0xFFFFFFFFu, m, o));
            M = fmaxf(M, __shfl_xor_sync(0xFFFFFFFFu, M, o));
        }
        if (lid == 0) { smin[wid] = m; smax[wid] = M; }
        __syncthreads();
        if (tid == 0) {
            float mm = smin[0], MM = smax[0];
            #pragma unroll
            for (int k = 1; k < 8; k++) { mm = fminf(mm, smin[k]); MM = fmaxf(MM, smax[k]); }
            float sigma = r[0] * (MM - mm);
            g_C = -4.0f * 1.4426950408889634f / (sigma * sigma);
            g_count = 0;   // reset for next graph replay
        }
    }
}

// ======================= main: packed-f32x2 bilateral + guided =======================
__global__ __launch_bounds__(BX * BY)
void k_main(float* __restrict__ out) {
    // SoA tiles; row strides even so even column index => 8B-aligned LDS.64
    __shared__ float sBX[26][52], sBY[26][52];  // base, halo 9 rows / 10 cols
    __shared__ float sDX[12][44], sDY[12][44];  // detail, halo 2 rows / 6 left 5 right

    const int tx = threadIdx.x, ty = threadIdx.y;
    const int j0 = blockIdx.x * BX, i0 = blockIdx.y * BY;
    const int tid = ty * BX + tx;

    for (int t = tid; t < 26 * 52; t += BX * BY) {
        int rr = t / 52, cc = t % 52;
        int gi = i0 - 9 + rr, gj = j0 - 10 + cc;
        float vx = 0.f, vy = 0.f;
        if ((unsigned)gi < W && (unsigned)gj < W) {
            vx = g_baseX[gi * W + gj]; vy = g_baseY[gi * W + gj];
        }
        sBX[rr][cc] = vx; sBY[rr][cc] = vy;
    }
    for (int t = tid; t < 12 * 44; t += BX * BY) {
        int rr = t / 44, cc = t % 44;
        int gi = i0 - 2 + rr, gj = j0 - 6 + cc;
        float vx = 0.f, vy = 0.f;
        if ((unsigned)gi < W && (unsigned)gj < W) {
            vx = g_detX[gi * W + gj]; vy = g_detY[gi * W + gj];
        }
        sDX[rr][cc] = vx; sDY[rr][cc] = vy;
    }
    __syncthreads();

    const int i = i0 + ty, j = j0 + tx;
    const int par = tx & 1;
    // chunk mapping: 63 + 7*62 + 15 = 512
    int chunk = (j <= 62) ? 0 : ((j >= 497) ? 8 : (j - 1) / 62);
    int s_ch = 62 * chunk;
    int e_ch = (chunk == 8) ? W : s_ch + 64;

    const float C = g_C;
    const u64 C2 = pk2(C, C);
    const u64 NEG1 = pk2(-1.0f, -1.0f);

    // ---------------- detail branch: 5x9 (+1 phantom col) ----------------
    {
        const int lcD = tx + 2 - par;              // even smem base col
        const float cdx = sDX[ty + 2][tx + 6];
        const u64 ncd2 = pk2(-cdx, -cdx);

        u64 ceD[5];
        #pragma unroll
        for (int k = 0; k < 5; k++) {
            float v01[2];
            #pragma unroll
            for (int h = 0; h < 2; h++) {
                int s = 2 * k + h;
                int dc = s - 4 - par;
                int c = j + dc;
                bool ok = (dc >= -4) && (dc <= 4) && (c >= s_ch) && (c < e_ch);
                v01[h] = ok ? -(float)(dc * dc) * KD : -1e30f;
            }
            ceD[k] = pk2(v01[0], v01[1]);
        }

        u64 wsD2 = 0, accD2 = 0;
        #pragma unroll 1
        for (int dr = -2; dr <= 2; dr++) {
            int rr = i + dr;
            if ((unsigned)rr >= W) continue;
            float rowf = -(float)(dr * dr) * KD;
            u64 ro2 = pk2(rowf, rowf);
            const float* rX = &sDX[ty + 2 + dr][lcD];
            const float* rY = &sDY[ty + 2 + dr][lcD];
            #pragma unroll
            for (int k = 0; k < 5; k++) {
                u64 vx = *(const u64*)(rX + 2 * k);
                u64 vy = *(const u64*)(rY + 2 * k);
                u64 d  = add2(vx, ncd2);
                u64 dd = mul2(d, d);
                u64 ea = fma2(dd, C2, add2(ceD[k], ro2));
                float e0, e1; upk2(e0, e1, ea);
                u64 w = pk2(ex2f(e0), ex2f(e1));
                u64 val = fma2(vx, NEG1, vy);       // vy - vx
                wsD2  = add2(wsD2, w);
                accD2 = fma2(w, val, accD2);
            }
        }
        float w0, w1, a0, a1;
        upk2(w0, w1, wsD2); upk2(a0, a1, accD2);
        float bdet = (a0 + a1) / (w0 + w1);

        // ---------------- base branch: 19x19 (+1 phantom col) ----------------
        const int lcB = tx + par;                  // even smem base col
        const float cbx = sBX[ty + 9][tx + 10];
        const u64 ncb2 = pk2(-cbx, -cbx);

        u64 ceB[10];
        #pragma unroll
        for (int k = 0; k < 10; k++) {
            float v01[2];
            #pragma unroll
            for (int h = 0; h < 2; h++) {
                int s = 2 * k + h;
                int dc = s - 10 + par;
                int c = j + dc;
                bool ok = (dc >= -9) && (dc <= 9) && (c >= s_ch) && (c < e_ch);
                v01[h] = ok ? -(float)(dc * dc) * KB : -1e30f;
            }
            ceB[k] = pk2(v01[0], v01[1]);
        }

        u64 ws2 = 0, sx2 = 0, sy2 = 0, sxx2 = 0, sxy2 = 0;
        #pragma unroll 1
        for (int dr = -9; dr <= 9; dr++) {
            int rr = i + dr;
            if ((unsigned)rr >= W) continue;
            float rowf = -(float)(dr * dr) * KB;
            u64 ro2 = pk2(rowf, rowf);
            const float* rX = &sBX[ty + 9 + dr][lcB];
            const float* rY = &sBY[ty + 9 + dr][lcB];
            #pragma unroll
            for (int k = 0; k < 10; k++) {
                u64 vx = *(const u64*)(rX + 2 * k);
                u64 vy = *(const u64*)(rY + 2 * k);
                u64 d  = add2(vx, ncb2);
                u64 dd = mul2(d, d);
                u64 ea = fma2(dd, C2, add2(ceB[k], ro2));
                float e0, e1; upk2(e0, e1, ea);
                u64 w = pk2(ex2f(e0), ex2f(e1));
                u64 t = mul2(w, vx);
                ws2  = add2(ws2, w);
                sx2  = add2(sx2, t);
                sy2  = fma2(w, vy, sy2);
                sxx2 = fma2(t, vx, sxx2);
                sxy2 = fma2(t, vy, sxy2);
            }
        }
        float p0, p1;
        upk2(p0, p1, ws2);  float ws  = p0 + p1;
        upk2(p0, p1, sx2);  float sx  = p0 + p1;
        upk2(p0, p1, sy2);  float sy  = p0 + p1;
        upk2(p0, p1, sxx2); float sxx = p0 + p1;
        upk2(p0, p1, sxy2); float sxy = p0 + p1;

        float rw   = 1.0f / ws;
        float mx   = sx * rw, my = sy * rw;
        float varx = fmaf(sxx, rw, -mx * mx);
        float cov  = fmaf(sxy, rw, -mx * my);
        float A = cov / (varx + 1e-6f);
        float b = my - A * mx;
        out[i * W + j] = fmaf(A, cbx, b) + cdx + bdet;
    }
}

extern "C" void kernel_launch(void* const* d_in, const int* in_sizes, int n_in,
                              void* d_out, int out_size) {
    const float* X = (const float*)d_in[0];
    const float* Y = (const float*)d_in[1];
    const float* r = (const float*)d_in[2];
    float* out = (float*)d_out;

    dim3 bp(32, 8), gp(16, 16);
    k_prep<<<gp, bp>>>(X, Y, r);

    dim3 bm(BX, BY), gm(W / BX, W / BY);
    k_main<<<gm, bm>>>(out);
}

// round 9
// speedup vs baseline: 1.1902x; 1.0185x over previous
#include <cuda_runtime.h>

#define W 512
#define BX 32
#define BY 8

// -------- scratch (no allocations allowed) --------
__device__ float  g_baseX[W * W];
__device__ float  g_baseY[W * W];
__device__ float  g_detX [W * W];
__device__ float  g_detV [W * W];   // (ydet - Xdet), pre-subtracted
__device__ float2 g_part[256];      // per-block (min,max) of y
__device__ int    g_count = 0;      // arrival counter (self-resetting)
__device__ float  g_C;              // -4*log2(e)/sigma^2

#define KB (1.4426950408889634f / 8145.0625f)   // base spatial, log2 units
#define KD (1.4426950408889634f / 126.5625f)    // detail spatial, log2 units

typedef unsigned long long u64;

__device__ __forceinline__ float ex2f(float a) {
    float r; asm("ex2.approx.f32 %0, %1;" : "=f"(r) : "f"(a)); return r;
}
__device__ __forceinline__ u64 pk2(float lo, float hi) {
    u64 r; asm("mov.b64 %0, {%1, %2};" : "=l"(r) : "f"(lo), "f"(hi)); return r;
}
__device__ __forceinline__ void upk2(float& lo, float& hi, u64 v) {
    asm("mov.b64 {%0, %1}, %2;" : "=f"(lo), "=f"(hi) : "l"(v));
}
__device__ __forceinline__ u64 add2(u64 a, u64 b) {
    u64 r; asm("add.rn.f32x2 %0, %1, %2;" : "=l"(r) : "l"(a), "l"(b)); return r;
}
__device__ __forceinline__ u64 mul2(u64 a, u64 b) {
    u64 r; asm("mul.rn.f32x2 %0, %1, %2;" : "=l"(r) : "l"(a), "l"(b)); return r;
}
__device__ __forceinline__ u64 fma2(u64 a, u64 b, u64 c) {
    u64 r; asm("fma.rn.f32x2 %0, %1, %2, %3;" : "=l"(r) : "l"(a), "l"(b), "l"(c)); return r;
}

// ======================= prep: 9x9 box + base/detail + sigma =======================
__global__ __launch_bounds__(256) void k_prep(const float* __restrict__ X,
                                              const float* __restrict__ Y,
                                              const float* __restrict__ r) {
    __shared__ float2 sIn[40][40];   // (X,Y) with halo 4
    __shared__ float2 sH[40][32];    // horizontal 9-sum
    __shared__ float  smin[8], smax[8];
    __shared__ int    isLast;

    const int tid = threadIdx.y * 32 + threadIdx.x;
    const int j0 = blockIdx.x * 32, i0 = blockIdx.y * 32;

    for (int t = tid; t < 40 * 40; t += 256) {
        int rr = t / 40, cc = t % 40;
        int gi = i0 - 4 + rr, gj = j0 - 4 + cc;
        float2 v = make_float2(0.f, 0.f);
        if ((unsigned)gi < W && (unsigned)gj < W) {
            v.x = X[gi * W + gj]; v.y = Y[gi * W + gj];
        }
        sIn[rr][cc] = v;
    }
    __syncthreads();

    for (int t = tid; t < 40 * 32; t += 256) {
        int rr = t / 32, cc = t % 32;
        float sx = 0.f, sy = 0.f;
        #pragma unroll
        for (int d = 0; d < 9; d++) { float2 v = sIn[rr][cc + d]; sx += v.x; sy += v.y; }
        sH[rr][cc] = make_float2(sx, sy);
    }
    __syncthreads();

    float lmin = 3.4e38f, lmax = -3.4e38f;
    for (int t = tid; t < 32 * 32; t += 256) {
        int rr = t / 32, cc = t % 32;
        float sx = 0.f, sy = 0.f;
        #pragma unroll
        for (int d = 0; d < 9; d++) { float2 v = sH[rr + d][cc]; sx += v.x; sy += v.y; }
        float bx = sx * (1.0f / 81.0f);
        float by = sy * (1.0f / 81.0f);
        float2 c = sIn[rr + 4][cc + 4];
        int idx = (i0 + rr) * W + (j0 + cc);
        float dx = c.x - bx, dy = c.y - by;
        g_baseX[idx] = bx;  g_baseY[idx] = by;
        g_detX [idx] = dx;  g_detV [idx] = dy - dx;
        lmin = fminf(lmin, c.y);  lmax = fmaxf(lmax, c.y);
    }

    #pragma unroll
    for (int o = 16; o; o >>= 1) {
        lmin = fminf(lmin, __shfl_xor_sync(0xFFFFFFFFu, lmin, o));
        lmax = fmaxf(lmax, __shfl_xor_sync(0xFFFFFFFFu, lmax, o));
    }
    int wid = tid >> 5, lid = tid & 31;
    if (lid == 0) { smin[wid] = lmin; smax[wid] = lmax; }
    __syncthreads();
    if (tid == 0) {
        float m = smin[0], M = smax[0];
        #pragma unroll
        for (int k = 1; k < 8; k++) { m = fminf(m, smin[k]); M = fmaxf(M, smax[k]); }
        g_part[blockIdx.y * 16 + blockIdx.x] = make_float2(m, M);
        __threadfence();
        int t = atomicAdd(&g_count, 1);
        isLast = (t == 255);
    }
    __syncthreads();
    if (isLast) {
        __threadfence();
        float2 p = g_part[tid];
        float m = p.x, M = p.y;
        #pragma unroll
        for (int o = 16; o; o >>= 1) {
            m = fminf(m, __shfl_xor_sync(0xFFFFFFFFu, m, o));
            M = fmaxf(M, __shfl_xor_sync(0xFFFFFFFFu, M, o));
        }
        if (lid == 0) { smin[wid] = m; smax[wid] = M; }
        __syncthreads();
        if (tid == 0) {
            float mm = smin[0], MM = smax[0];
            #pragma unroll
            for (int k = 1; k < 8; k++) { mm = fminf(mm, smin[k]); MM = fmaxf(MM, smax[k]); }
            float sigma = r[0] * (MM - mm);
            g_C = -4.0f * 1.4426950408889634f / (sigma * sigma);
            g_count = 0;   // reset for next graph replay
        }
    }
}

// ======================= main: packed-f32x2 bilateral + guided =======================
__global__ __launch_bounds__(BX * BY, 5)
void k_main(float* __restrict__ out) {
    // SoA tiles; row strides even so even column index => 8B-aligned LDS.64
    __shared__ float sBX[26][52], sBY[26][52];  // base, halo 9 rows / 10 cols
    __shared__ float sDX[12][44], sDY[12][44];  // detail X and (ydet-Xdet)
    __shared__ u64 espB[10][32];                // per-column packed exponent offsets
    __shared__ u64 espD[5][32];

    const int tx = threadIdx.x, ty = threadIdx.y;
    const int j0 = blockIdx.x * BX, i0 = blockIdx.y * BY;
    const int tid = ty * BX + tx;
    const int par = tx & 1;
    const int j = j0 + tx;

    // build per-column exponent tables (spatial + phantom/chunk mask folded in)
    if (ty == 0) {
        int chunk = (j <= 62) ? 0 : ((j >= 497) ? 8 : (j - 1) / 62);
        int s_ch = 62 * chunk;
        int e_ch = (chunk == 8) ? W : s_ch + 64;
        #pragma unroll
        for (int k = 0; k < 10; k++) {
            float v01[2];
            #pragma unroll
            for (int h = 0; h < 2; h++) {
                int s = 2 * k + h;
                int dc = s - 10 + par;
                int c = j + dc;
                bool ok = (dc >= -9) && (dc <= 9) && (c >= s_ch) && (c < e_ch);
                v01[h] = ok ? -(float)(dc * dc) * KB : -1e30f;
            }
            espB[k][tx] = pk2(v01[0], v01[1]);
        }
        #pragma unroll
        for (int k = 0; k < 5; k++) {
            float v01[2];
            #pragma unroll
            for (int h = 0; h < 2; h++) {
                int s = 2 * k + h;
                int dc = s - 4 - par;
                int c = j + dc;
                bool ok = (dc >= -4) && (dc <= 4) && (c >= s_ch) && (c < e_ch);
                v01[h] = ok ? -(float)(dc * dc) * KD : -1e30f;
            }
            espD[k][tx] = pk2(v01[0], v01[1]);
        }
    }

    for (int t = tid; t < 26 * 52; t += BX * BY) {
        int rr = t / 52, cc = t % 52;
        int gi = i0 - 9 + rr, gj = j0 - 10 + cc;
        float vx = 0.f, vy = 0.f;
        if ((unsigned)gi < W && (unsigned)gj < W) {
            vx = g_baseX[gi * W + gj]; vy = g_baseY[gi * W + gj];
        }
        sBX[rr][cc] = vx; sBY[rr][cc] = vy;
    }
    for (int t = tid; t < 12 * 44; t += BX * BY) {
        int rr = t / 44, cc = t % 44;
        int gi = i0 - 2 + rr, gj = j0 - 6 + cc;
        float vx = 0.f, vy = 0.f;
        if ((unsigned)gi < W && (unsigned)gj < W) {
            vx = g_detX[gi * W + gj]; vy = g_detV[gi * W + gj];
        }
        sDX[rr][cc] = vx; sDY[rr][cc] = vy;
    }
    __syncthreads();

    const int i = i0 + ty;
    const float C = g_C;
    const u64 C2 = pk2(C, C);

    // ---------------- detail branch: 5x9 (+1 phantom col) ----------------
    const int lcD = tx + 2 - par;              // even smem base col
    const float cdx = sDX[ty + 2][tx + 6];
    const u64 ncd2 = pk2(-cdx, -cdx);

    u64 wsD2 = 0, accD2 = 0;
    #pragma unroll 1
    for (int dr = -2; dr <= 2; dr++) {
        int rr = i + dr;
        if ((unsigned)rr >= W) continue;
        float rowf = -(float)(dr * dr) * KD;
        u64 ro2 = pk2(rowf, rowf);
        const float* rX = &sDX[ty + 2 + dr][lcD];
        const float* rY = &sDY[ty + 2 + dr][lcD];
        #pragma unroll
        for (int k = 0; k < 5; k++) {
            u64 vx = *(const u64*)(rX + 2 * k);
            u64 vy = *(const u64*)(rY + 2 * k);
            u64 d  = add2(vx, ncd2);
            u64 dd = mul2(d, d);
            u64 ea = fma2(dd, C2, add2(espD[k][tx], ro2));
            float e0, e1; upk2(e0, e1, ea);
            u64 w = pk2(ex2f(e0), ex2f(e1));
            wsD2  = add2(wsD2, w);
            accD2 = fma2(w, vy, accD2);            // vy already (ydet - Xdet)
        }
    }
    float w0, w1, a0, a1;
    upk2(w0, w1, wsD2); upk2(a0, a1, accD2);
    float bdet = (a0 + a1) / (w0 + w1);

    // ---------------- base branch: 19x19 (+1 phantom col) ----------------
    const int lcB = tx + par;                  // even smem base col
    const float cbx = sBX[ty + 9][tx + 10];
    const u64 ncb2 = pk2(-cbx, -cbx);

    u64 ws2 = 0, sx2 = 0, sy2 = 0, sxx2 = 0, sxy2 = 0;
    #pragma unroll 1
    for (int dr = -9; dr <= 9; dr++) {
        int rr = i + dr;
        if ((unsigned)rr >= W) continue;
        float rowf = -(float)(dr * dr) * KB;
        u64 ro2 = pk2(rowf, rowf);
        const float* rX = &sBX[ty + 9 + dr][lcB];
        const float* rY = &sBY[ty + 9 + dr][lcB];
        #pragma unroll
        for (int k = 0; k < 10; k++) {
            u64 vx = *(const u64*)(rX + 2 * k);
            u64 vy = *(const u64*)(rY + 2 * k);
            u64 d  = add2(vx, ncb2);
            u64 dd = mul2(d, d);
            u64 ea = fma2(dd, C2, add2(espB[k][tx], ro2));
            float e0, e1; upk2(e0, e1, ea);
            u64 w = pk2(ex2f(e0), ex2f(e1));
            u64 t = mul2(w, vx);
            ws2  = add2(ws2, w);
            sx2  = add2(sx2, t);
            sy2  = fma2(w, vy, sy2);
            sxx2 = fma2(t, vx, sxx2);
            sxy2 = fma2(t, vy, sxy2);
        }
    }
    float p0, p1;
    upk2(p0, p1, ws2);  float ws  = p0 + p1;
    upk2(p0, p1, sx2);  float sx  = p0 + p1;
    upk2(p0, p1, sy2);  float sy  = p0 + p1;
    upk2(p0, p1, sxx2); float sxx = p0 + p1;
    upk2(p0, p1, sxy2); float sxy = p0 + p1;

    float rw   = 1.0f / ws;
    float mx   = sx * rw, my = sy * rw;
    float varx = fmaf(sxx, rw, -mx * mx);
    float cov  = fmaf(sxy, rw, -mx * my);
    float A = cov / (varx + 1e-6f);
    float b = my - A * mx;
    out[i * W + j] = fmaf(A, cbx, b) + cdx + bdet;
}

extern "C" void kernel_launch(void* const* d_in, const int* in_sizes, int n_in,
                              void* d_out, int out_size) {
    const float* X = (const float*)d_in[0];
    const float* Y = (const float*)d_in[1];
    const float* r = (const float*)d_in[2];
    float* out = (float*)d_out;

    dim3 bp(32, 8), gp(16, 16);
    k_prep<<<gp, bp>>>(X, Y, r);

    dim3 bm(BX, BY), gm(W / BX, W / BY);
    k_main<<<gm, bm>>>(out);
}